// round 5
// baseline (speedup 1.0000x reference)
#include <cuda_runtime.h>
#include <math.h>
#include <stdint.h>

constexpr int kT    = 1024;
constexpr int kH    = 1024;
constexpr int kI    = 512;
constexpr int kE    = 16;
constexpr int kEAll = 18;     // + 2 shared-expert halves
constexpr int kTopK = 4;
constexpr int kNG   = 4;
constexpr int kGS   = kE / kNG;
constexpr int kTKG  = 2;
constexpr int kISH  = 1024;
constexpr float kScale = 2.5f;

// ---- device scratch ----
__device__ int   g_cnt[kEAll];
__device__ int   g_tok[kEAll * kT];
__device__ float g_coef[kEAll * kT];
__device__ int   g_tslot[kT * kTopK];
__device__ float g_h[(size_t)kEAll * kT * kI];    // per-slot hidden
__device__ float g_o[(size_t)kEAll * kT * kH];    // per-slot down output

// ---------------------------------------------------------------------------
__device__ __forceinline__ float tf32r(float f) {
    uint32_t r; asm("cvt.rna.tf32.f32 %0, %1;" : "=r"(r) : "f"(f));
    return __uint_as_float(r);
}
__device__ __forceinline__ void mma8(float* c,
                                     uint32_t a0, uint32_t a1, uint32_t a2, uint32_t a3,
                                     uint32_t b0, uint32_t b1) {
    asm volatile("mma.sync.aligned.m16n8k8.row.col.f32.tf32.tf32.f32 "
                 "{%0,%1,%2,%3},{%4,%5,%6,%7},{%8,%9},{%0,%1,%2,%3};\n"
                 : "+f"(c[0]), "+f"(c[1]), "+f"(c[2]), "+f"(c[3])
                 : "r"(a0), "r"(a1), "r"(a2), "r"(a3), "r"(b0), "r"(b1));
}

// ---------------------------------------------------------------------------
__global__ void init_kernel() {
    int i = blockIdx.x * blockDim.x + threadIdx.x;
    if (i < kE) g_cnt[i] = 0;
    if (i == kE || i == kE + 1) g_cnt[i] = kT;
    if (i < kT) {
        g_tok[kE * kT + i] = i;       g_coef[kE * kT + i] = 1.f;
        g_tok[(kE + 1) * kT + i] = i; g_coef[(kE + 1) * kT + i] = 1.f;
    }
}

// ---------------------------------------------------------------------------
__global__ __launch_bounds__(512) void router_kernel(
    const float* __restrict__ x, const float* __restrict__ rw,
    const float* __restrict__ ebias)
{
    const int t = blockIdx.x;
    const int warp = threadIdx.x >> 5;
    const int lane = threadIdx.x & 31;
    __shared__ float logits[kE];

    const float* xr = x + (size_t)t * kH;
    float acc = 0.f;
    for (int h = lane; h < kH; h += 32)
        acc += xr[h] * rw[h * kE + warp];
    #pragma unroll
    for (int o = 16; o; o >>= 1) acc += __shfl_xor_sync(0xffffffffu, acc, o);
    if (lane == 0) logits[warp] = acc;
    __syncthreads();

    if (threadIdx.x == 0) {
        float scores[kE], sc[kE];
        #pragma unroll
        for (int e = 0; e < kE; e++) {
            float s = 1.f / (1.f + expf(-logits[e]));
            scores[e] = s;
            sc[e] = s + ebias[e];
        }
        float gs[kNG];
        #pragma unroll
        for (int g = 0; g < kNG; g++) {
            float m1 = -1e30f, m2 = -1e30f;
            #pragma unroll
            for (int j = 0; j < kGS; j++) {
                float v = sc[g * kGS + j];
                if (v > m1) { m2 = m1; m1 = v; }
                else if (v > m2) m2 = v;
            }
            gs[g] = m1 + m2;
        }
        bool gsel[kNG] = {false, false, false, false};
        for (int k = 0; k < kTKG; k++) {
            int bi = -1; float bv = -1e30f;
            for (int g = 0; g < kNG; g++)
                if (!gsel[g] && gs[g] > bv) { bv = gs[g]; bi = g; }
            gsel[bi] = true;
        }
        float masked[kE];
        #pragma unroll
        for (int e = 0; e < kE; e++)
            masked[e] = gsel[e / kGS] ? sc[e] : 0.f;
        int tidx[kTopK]; float w[kTopK]; float wsum = 0.f;
        bool used[kE];
        #pragma unroll
        for (int e = 0; e < kE; e++) used[e] = false;
        for (int k = 0; k < kTopK; k++) {
            int bi = -1; float bv = -1e30f;
            for (int e = 0; e < kE; e++)
                if (!used[e] && masked[e] > bv) { bv = masked[e]; bi = e; }
            used[bi] = true;
            tidx[k] = bi;
            w[k] = scores[bi];
            wsum += w[k];
        }
        float inv = kScale / (wsum + 1e-20f);
        for (int k = 0; k < kTopK; k++) {
            int e = tidx[k];
            int slot = atomicAdd(&g_cnt[e], 1);
            g_tok[e * kT + slot]  = t;
            g_coef[e * kT + slot] = w[k] * inv;
            g_tslot[t * kTopK + k] = e * kT + slot;
        }
    }
}

// ---------------------------------------------------------------------------
// Gate+up: CTA 128 rows x 128 I-cols (staged as 256 smem cols: per 64-col
// warp block, [32 gate | 32 up]). 8 warps, warp tile 64x64 (=64x32 g + 64x32 u,
// shared A fragment). tf32 mma m16n8k8, K-chunk 16, register prefetch.
__global__ __launch_bounds__(256, 1) void gateup_v2(
    const float* __restrict__ x, const float* __restrict__ wg,
    const float* __restrict__ wu, const float* __restrict__ swg,
    const float* __restrict__ swu)
{
    const int e = blockIdx.z;
    const int cnt = g_cnt[e];
    const int row0 = blockIdx.y * 128;
    if (row0 >= cnt) return;
    const int col0 = blockIdx.x * 128;

    __shared__ float As[128 * 20];    // [m][k], stride 20
    __shared__ float Bs[16 * 264];    // [k][s], stride 264, s: 4 x (32g|32u)

    const int tid = threadIdx.x;
    const int w = tid >> 5, l = tid & 31;
    const int qr = l >> 2, qc = l & 3;
    const int mw = (w & 1) * 64, wc = w >> 1;    // wc: 0..3

    const float *gbase, *ubase; int ldb;
    if (e < kE) {
        gbase = wg + (size_t)e * kH * kI;
        ubase = wu + (size_t)e * kH * kI;
        ldb = kI;
    } else {
        int off = (e - kE) * kI;
        gbase = swg + off; ubase = swu + off; ldb = kISH;
    }

    // A staging: 2 float4/thread, gathered token rows
    const float* aptr[2]; int aso[2];
    #pragma unroll
    for (int p = 0; p < 2; p++) {
        int j = tid + 256 * p;
        int ar = j >> 2, kq = (j & 3) * 4;
        int slot = row0 + ar; if (slot >= cnt) slot = cnt - 1;
        aptr[p] = x + (size_t)g_tok[e * kT + slot] * kH + kq;
        aso[p] = ar * 20 + kq;
    }
    // B staging: 4 float4/thread, interleaved g/u blocks
    const float* bptr[4]; int bso[4];
    #pragma unroll
    for (int p = 0; p < 4; p++) {
        int j = tid + 256 * p;
        int k = j >> 6;            // 0..15
        int sq = (j & 63) * 4;     // smem col 0..252
        int bwc = sq >> 6, j4 = sq & 63;
        int srccol = col0 + bwc * 32 + (j4 < 32 ? j4 : j4 - 32);
        bptr[p] = (j4 < 32 ? gbase : ubase) + (size_t)k * ldb + srccol;
        bso[p] = k * 264 + sq;
    }

    float c[4][8][4] = {};   // [mt][nt] nt<4: gate, nt>=4: up

    float4 ra[2], rb[4];
    #pragma unroll
    for (int p = 0; p < 2; p++) ra[p] = *(const float4*)aptr[p];
    #pragma unroll
    for (int p = 0; p < 4; p++) rb[p] = *(const float4*)bptr[p];

    constexpr int NCH = kH / 16;
    for (int ch = 0; ch < NCH; ch++) {
        #pragma unroll
        for (int p = 0; p < 2; p++) {
            float4 v; v.x = tf32r(ra[p].x); v.y = tf32r(ra[p].y);
            v.z = tf32r(ra[p].z); v.w = tf32r(ra[p].w);
            *(float4*)&As[aso[p]] = v;
        }
        #pragma unroll
        for (int p = 0; p < 4; p++) {
            float4 v; v.x = tf32r(rb[p].x); v.y = tf32r(rb[p].y);
            v.z = tf32r(rb[p].z); v.w = tf32r(rb[p].w);
            *(float4*)&Bs[bso[p]] = v;
        }
        __syncthreads();
        if (ch + 1 < NCH) {
            #pragma unroll
            for (int p = 0; p < 2; p++) { aptr[p] += 16; ra[p] = *(const float4*)aptr[p]; }
            #pragma unroll
            for (int p = 0; p < 4; p++) { bptr[p] += (size_t)16 * ldb; rb[p] = *(const float4*)bptr[p]; }
        }
        #pragma unroll
        for (int ks = 0; ks < 16; ks += 8) {
            uint32_t af[4][4];
            #pragma unroll
            for (int mt = 0; mt < 4; mt++) {
                int m = mw + mt * 16;
                af[mt][0] = __float_as_uint(As[(m + qr) * 20 + ks + qc]);
                af[mt][1] = __float_as_uint(As[(m + qr + 8) * 20 + ks + qc]);
                af[mt][2] = __float_as_uint(As[(m + qr) * 20 + ks + qc + 4]);
                af[mt][3] = __float_as_uint(As[(m + qr + 8) * 20 + ks + qc + 4]);
            }
            #pragma unroll
            for (int nt = 0; nt < 8; nt++) {
                int n = wc * 64 + nt * 8 + qr;
                uint32_t b0 = __float_as_uint(Bs[(ks + qc) * 264 + n]);
                uint32_t b1 = __float_as_uint(Bs[(ks + qc + 4) * 264 + n]);
                #pragma unroll
                for (int mt = 0; mt < 4; mt++)
                    mma8(c[mt][nt], af[mt][0], af[mt][1], af[mt][2], af[mt][3], b0, b1);
            }
        }
        __syncthreads();
    }

    // Epilogue: h = coef * silu(g) * u (tf32 pre-rounded for the down GEMM)
    #pragma unroll
    for (int mt = 0; mt < 4; mt++) {
        #pragma unroll
        for (int pair = 0; pair < 2; pair++) {
            int r = row0 + mw + mt * 16 + qr + pair * 8;
            if (r < cnt) {
                float cf = g_coef[e * kT + r];
                float* hp = g_h + ((size_t)e * kT + r) * kI + col0 + wc * 32;
                #pragma unroll
                for (int nt = 0; nt < 4; nt++) {
                    float g0 = c[mt][nt][pair * 2 + 0];
                    float g1 = c[mt][nt][pair * 2 + 1];
                    float u0 = c[mt][nt + 4][pair * 2 + 0];
                    float u1 = c[mt][nt + 4][pair * 2 + 1];
                    float h0 = cf * (g0 / (1.f + __expf(-g0))) * u0;
                    float h1 = cf * (g1 / (1.f + __expf(-g1))) * u1;
                    float2 st; st.x = tf32r(h0); st.y = tf32r(h1);
                    *(float2*)&hp[nt * 8 + 2 * qc] = st;
                }
            }
        }
    }
}

// ---------------------------------------------------------------------------
// Down-proj: CTA 128 rows x 256 H-cols, 8 warps, warp tile 64x64.
// Writes per-slot rows to g_o (no atomics); combine gathers.
__global__ __launch_bounds__(256, 1) void down_v2(
    const float* __restrict__ wd, const float* __restrict__ swd)
{
    const int e = blockIdx.z;
    const int cnt = g_cnt[e];
    const int row0 = blockIdx.y * 128;
    if (row0 >= cnt) return;
    const int col0 = blockIdx.x * 256;

    __shared__ float As[128 * 20];
    __shared__ float Bs[16 * 264];

    const int tid = threadIdx.x;
    const int w = tid >> 5, l = tid & 31;
    const int qr = l >> 2, qc = l & 3;
    const int mw = (w & 1) * 64, nw = (w >> 1) * 64;

    const float* bw = (e < kE) ? (wd + (size_t)e * kI * kH)
                               : (swd + (size_t)(e - kE) * kI * kH);

    const float* aptr[2]; int aso[2];
    #pragma unroll
    for (int p = 0; p < 2; p++) {
        int j = tid + 256 * p;
        int ar = j >> 2, kq = (j & 3) * 4;
        aptr[p] = g_h + ((size_t)e * kT + row0 + ar) * kI + kq;
        aso[p] = ar * 20 + kq;
    }
    const float* bptr[4]; int bso[4];
    #pragma unroll
    for (int p = 0; p < 4; p++) {
        int j = tid + 256 * p;
        int k = j >> 6, nq = (j & 63) * 4;
        bptr[p] = bw + (size_t)k * kH + col0 + nq;
        bso[p] = k * 264 + nq;
    }

    float c[4][8][4] = {};

    float4 ra[2], rb[4];
    #pragma unroll
    for (int p = 0; p < 2; p++) ra[p] = *(const float4*)aptr[p];
    #pragma unroll
    for (int p = 0; p < 4; p++) rb[p] = *(const float4*)bptr[p];

    constexpr int NCH = kI / 16;
    for (int ch = 0; ch < NCH; ch++) {
        #pragma unroll
        for (int p = 0; p < 2; p++)
            *(float4*)&As[aso[p]] = ra[p];   // g_h already tf32-rounded
        #pragma unroll
        for (int p = 0; p < 4; p++) {
            float4 v; v.x = tf32r(rb[p].x); v.y = tf32r(rb[p].y);
            v.z = tf32r(rb[p].z); v.w = tf32r(rb[p].w);
            *(float4*)&Bs[bso[p]] = v;
        }
        __syncthreads();
        if (ch + 1 < NCH) {
            #pragma unroll
            for (int p = 0; p < 2; p++) { aptr[p] += 16; ra[p] = *(const float4*)aptr[p]; }
            #pragma unroll
            for (int p = 0; p < 4; p++) { bptr[p] += (size_t)16 * kH; rb[p] = *(const float4*)bptr[p]; }
        }
        #pragma unroll
        for (int ks = 0; ks < 16; ks += 8) {
            uint32_t af[4][4];
            #pragma unroll
            for (int mt = 0; mt < 4; mt++) {
                int m = mw + mt * 16;
                af[mt][0] = __float_as_uint(As[(m + qr) * 20 + ks + qc]);
                af[mt][1] = __float_as_uint(As[(m + qr + 8) * 20 + ks + qc]);
                af[mt][2] = __float_as_uint(As[(m + qr) * 20 + ks + qc + 4]);
                af[mt][3] = __float_as_uint(As[(m + qr + 8) * 20 + ks + qc + 4]);
            }
            #pragma unroll
            for (int nt = 0; nt < 8; nt++) {
                int n = nw + nt * 8 + qr;
                uint32_t b0 = __float_as_uint(Bs[(ks + qc) * 264 + n]);
                uint32_t b1 = __float_as_uint(Bs[(ks + qc + 4) * 264 + n]);
                #pragma unroll
                for (int mt = 0; mt < 4; mt++)
                    mma8(c[mt][nt], af[mt][0], af[mt][1], af[mt][2], af[mt][3], b0, b1);
            }
        }
        __syncthreads();
    }

    #pragma unroll
    for (int mt = 0; mt < 4; mt++) {
        #pragma unroll
        for (int pair = 0; pair < 2; pair++) {
            int r = row0 + mw + mt * 16 + qr + pair * 8;
            if (r < cnt) {
                float* op = g_o + ((size_t)e * kT + r) * kH + col0 + nw;
                #pragma unroll
                for (int nt = 0; nt < 8; nt++) {
                    float2 st;
                    st.x = c[mt][nt][pair * 2 + 0];
                    st.y = c[mt][nt][pair * 2 + 1];
                    *(float2*)&op[nt * 8 + 2 * qc] = st;
                }
            }
        }
    }
}

// ---------------------------------------------------------------------------
// Combine: out[t] = sum of 4 routed slot rows + 2 shared slot rows.
__global__ __launch_bounds__(256) void combine_kernel(float* __restrict__ out) {
    const int t = blockIdx.x;
    const int c = threadIdx.x * 4;
    int s0 = g_tslot[t * kTopK + 0], s1 = g_tslot[t * kTopK + 1];
    int s2 = g_tslot[t * kTopK + 2], s3 = g_tslot[t * kTopK + 3];
    float4 a = *(const float4*)&g_o[(size_t)s0 * kH + c];
    float4 b = *(const float4*)&g_o[(size_t)s1 * kH + c];
    float4 d = *(const float4*)&g_o[(size_t)s2 * kH + c];
    float4 e4 = *(const float4*)&g_o[(size_t)s3 * kH + c];
    float4 f = *(const float4*)&g_o[((size_t)kE * kT + t) * kH + c];
    float4 g = *(const float4*)&g_o[((size_t)(kE + 1) * kT + t) * kH + c];
    float4 r;
    r.x = a.x + b.x + d.x + e4.x + f.x + g.x;
    r.y = a.y + b.y + d.y + e4.y + f.y + g.y;
    r.z = a.z + b.z + d.z + e4.z + f.z + g.z;
    r.w = a.w + b.w + d.w + e4.w + f.w + g.w;
    *(float4*)&out[(size_t)t * kH + c] = r;
}

// ---------------------------------------------------------------------------
extern "C" void kernel_launch(void* const* d_in, const int* in_sizes, int n_in,
                              void* d_out, int out_size) {
    const float* x   = (const float*)d_in[0];
    const float* rw  = (const float*)d_in[1];
    const float* eb  = (const float*)d_in[2];
    const float* wg  = (const float*)d_in[3];
    const float* wu  = (const float*)d_in[4];
    const float* wd  = (const float*)d_in[5];
    const float* swg = (const float*)d_in[6];
    const float* swu = (const float*)d_in[7];
    const float* swd = (const float*)d_in[8];
    float* out = (float*)d_out;

    init_kernel<<<4, 256>>>();
    router_kernel<<<kT, 512>>>(x, rw, eb);
    gateup_v2<<<dim3(4, 8, kEAll), 256>>>(x, wg, wu, swg, swu);
    down_v2<<<dim3(4, 8, kEAll), 256>>>(wd, swd);
    combine_kernel<<<kT, 256>>>(out);
}